// round 15
// baseline (speedup 1.0000x reference)
#include <cuda_runtime.h>
#include <cuda_fp16.h>
#include <math.h>
#include <stdint.h>

// Problem constants (fixed for this problem instance)
#define NMAX   50000
#define EMAX   800000
#define F_IN   512
#define H1     256
#define H2     16
#define F_OUT  40

#define SCAN_B 256

// Scratch (static device arrays; no allocation allowed)
__device__ __half g_xh[NMAX * F_IN];        // x in fp16
__device__ __half g_w1t[H1 * F_IN];         // W1 transposed [m][k], fp16
__device__ unsigned char g_p1f8[NMAX * H1]; // dinv ⊙ (x @ W1), fp8 e4m3
__device__ __half g_a1h[NMAX * H1];         // relu(Ahat h1 + b1), fp16
__device__ __half g_p2h[NMAX * H2];         // dinv ⊙ (a1 @ W2), fp16
__device__ __half g_p3h[NMAX * H2];         // dinv ⊙ relu(Ahat h2 + b2), fp16
__device__ int   g_deg[NMAX];
__device__ int   g_rowstart[NMAX];
__device__ int   g_cursor[NMAX];
__device__ int   g_csrc[EMAX];
__device__ int   g_bsum[SCAN_B];
__device__ float g_dinv[NMAX];

__device__ __forceinline__ void h8unpack(float f[8], uint4 v) {
    const __half2* h = (const __half2*)&v;
#pragma unroll
    for (int i = 0; i < 4; i++) {
        float2 t = __half22float2(h[i]);
        f[2 * i] = t.x;
        f[2 * i + 1] = t.y;
    }
}

__device__ __forceinline__ void h8addf(float acc[8], uint4 v) {
    const __half2* h = (const __half2*)&v;
#pragma unroll
    for (int i = 0; i < 4; i++) {
        float2 t = __half22float2(h[i]);
        acc[2 * i]     += t.x;
        acc[2 * i + 1] += t.y;
    }
}

// unpack 8 fp8 (uint2) into 4 half2 accumulators
__device__ __forceinline__ void fp8x8_add(__half2 acc[4], uint2 v) {
    unsigned short s0 = (unsigned short)(v.x & 0xffff);
    unsigned short s1 = (unsigned short)(v.x >> 16);
    unsigned short s2 = (unsigned short)(v.y & 0xffff);
    unsigned short s3 = (unsigned short)(v.y >> 16);
    uint32_t h0, h1, h2, h3;
    asm("cvt.rn.f16x2.e4m3x2 %0, %1;" : "=r"(h0) : "h"(s0));
    asm("cvt.rn.f16x2.e4m3x2 %0, %1;" : "=r"(h1) : "h"(s1));
    asm("cvt.rn.f16x2.e4m3x2 %0, %1;" : "=r"(h2) : "h"(s2));
    asm("cvt.rn.f16x2.e4m3x2 %0, %1;" : "=r"(h3) : "h"(s3));
    acc[0] = __hadd2(acc[0], *(__half2*)&h0);
    acc[1] = __hadd2(acc[1], *(__half2*)&h1);
    acc[2] = __hadd2(acc[2], *(__half2*)&h2);
    acc[3] = __hadd2(acc[3], *(__half2*)&h3);
}

// ---------------------------------------------------------------------------
// conversions
// ---------------------------------------------------------------------------
__global__ void convert_x_kernel(const float* __restrict__ x, long total8) {
    long i = (long)blockIdx.x * blockDim.x + threadIdx.x;
    if (i < total8) {
        float4 a = ((const float4*)x)[2 * i];
        float4 b = ((const float4*)x)[2 * i + 1];
        uint4 v;
        ((__half2*)&v)[0] = __floats2half2_rn(a.x, a.y);
        ((__half2*)&v)[1] = __floats2half2_rn(a.z, a.w);
        ((__half2*)&v)[2] = __floats2half2_rn(b.x, b.y);
        ((__half2*)&v)[3] = __floats2half2_rn(b.z, b.w);
        ((uint4*)g_xh)[i] = v;
    }
}

__global__ void convert_w1t_kernel(const float* __restrict__ W1) {
    int i = blockIdx.x * blockDim.x + threadIdx.x;   // over H1*F_IN
    if (i < H1 * F_IN) {
        int m = i >> 9;          // /512
        int k = i & 511;
        g_w1t[i] = __float2half_rn(W1[k * H1 + m]);
    }
}

// ---------------------------------------------------------------------------
// degree / dinv / scan / CSR fill
// ---------------------------------------------------------------------------
__global__ void zero_deg_kernel(int N) {
    int i = blockIdx.x * blockDim.x + threadIdx.x;
    if (i < N) g_deg[i] = 0;
}

__global__ void count_deg_kernel(const int* __restrict__ ei, int E, int N) {
    int e = blockIdx.x * blockDim.x + threadIdx.x;
    if (e < E) {
        int d = ei[E + e];
        if ((unsigned)d < (unsigned)N) atomicAdd(&g_deg[d], 1);
    }
}

__global__ void dinv_kernel(int N) {
    int i = blockIdx.x * blockDim.x + threadIdx.x;
    if (i < N) g_dinv[i] = rsqrtf((float)(g_deg[i] + 1));   // +1 self-loop
}

__global__ void scan_partial_kernel(int N) {
    __shared__ int sd[SCAN_B];
    int t = threadIdx.x, b = blockIdx.x;
    int i = b * SCAN_B + t;
    int v = (i < N) ? g_deg[i] : 0;
    sd[t] = v;
    __syncthreads();
#pragma unroll
    for (int off = 1; off < SCAN_B; off <<= 1) {
        int x = (t >= off) ? sd[t - off] : 0;
        __syncthreads();
        sd[t] += x;
        __syncthreads();
    }
    if (i < N) g_rowstart[i] = sd[t] - v;       // exclusive
    if (t == SCAN_B - 1) g_bsum[b] = sd[t];
}

__global__ void scan_bsum_kernel(int nblk) {
    __shared__ int sd[SCAN_B];
    int t = threadIdx.x;
    int v = (t < nblk) ? g_bsum[t] : 0;
    sd[t] = v;
    __syncthreads();
#pragma unroll
    for (int off = 1; off < SCAN_B; off <<= 1) {
        int x = (t >= off) ? sd[t - off] : 0;
        __syncthreads();
        sd[t] += x;
        __syncthreads();
    }
    if (t < nblk) g_bsum[t] = sd[t] - v;
}

__global__ void scan_add_kernel(int N) {
    int i = blockIdx.x * blockDim.x + threadIdx.x;
    if (i < N) {
        int r = g_rowstart[i] + g_bsum[i / SCAN_B];
        g_rowstart[i] = r;
        g_cursor[i] = r;
    }
}

__global__ void csr_fill_kernel(const int* __restrict__ ei, int E, int N) {
    int e = blockIdx.x * blockDim.x + threadIdx.x;
    if (e < E) {
        int s = ei[e];
        int d = ei[E + e];
        if ((unsigned)s < (unsigned)N && (unsigned)d < (unsigned)N) {
            int pos = atomicAdd(&g_cursor[d], 1);
            g_csrc[pos] = s;
        }
    }
}

// ---------------------------------------------------------------------------
// GEMM1 (fp16 tensor cores, mma.m16n8k16, fp32 accum, cp.async 3-stage,
// ldmatrix A+B): g_p1f8 = fp8(dinv ⊙ (xh @ W1))
// ---------------------------------------------------------------------------
#define G1_BM 128
#define G1_BN 128
#define G1_BK 32
#define G1_KT (F_IN / G1_BK)   // 16 k-tiles
#define STAGES 3
#define HS_STRIDE 40           // halves; 80B rows, conflict-free ldmatrix

__device__ __forceinline__ void mma_f16(float c[4], const uint32_t a[4],
                                        const uint32_t b[2]) {
    asm volatile(
        "mma.sync.aligned.m16n8k16.row.col.f32.f16.f16.f32 "
        "{%0,%1,%2,%3}, {%4,%5,%6,%7}, {%8,%9}, {%0,%1,%2,%3};"
        : "+f"(c[0]), "+f"(c[1]), "+f"(c[2]), "+f"(c[3])
        : "r"(a[0]), "r"(a[1]), "r"(a[2]), "r"(a[3]), "r"(b[0]), "r"(b[1]));
}

__device__ __forceinline__ void cp_async16(uint32_t smem_dst, const void* gsrc,
                                           int src_bytes) {
    asm volatile("cp.async.ca.shared.global [%0], [%1], 16, %2;"
                 :: "r"(smem_dst), "l"(gsrc), "r"(src_bytes));
}

__device__ __forceinline__ unsigned short pack_e4m3x2(float hi, float lo) {
    unsigned short u;
    asm("cvt.rn.satfinite.e4m3x2.f32 %0, %1, %2;" : "=h"(u) : "f"(hi), "f"(lo));
    return u;
}

__global__ void __launch_bounds__(256) gemm1_kernel(int N) {
    __shared__ __half As[STAGES][G1_BM * HS_STRIDE];   // 30 KB
    __shared__ __half Bs[STAGES][G1_BN * HS_STRIDE];   // 30 KB

    int tid = threadIdx.x;
    int lane = tid & 31;
    int w = tid >> 5;
    int wm = w >> 2;
    int wn = w & 3;
    int brow = blockIdx.y * G1_BM;
    int bcol = blockIdx.x * G1_BN;

    int ldrow = tid >> 1;
    int ldoff = (tid & 1) * 16;

    int gr = brow + ldrow;
    int a_ok = (gr < N) ? 16 : 0;
    const __half* a_src0 = &g_xh[(long)gr * F_IN + ldoff];
    const __half* b_src0 = &g_w1t[(long)(bcol + ldrow) * F_IN + ldoff];

    auto load_stage = [&](int st, int k0) {
        uint32_t ad = (uint32_t)__cvta_generic_to_shared(
            &As[st][ldrow * HS_STRIDE + ldoff]);
        cp_async16(ad, a_src0 + k0, a_ok);
        cp_async16(ad + 16, a_src0 + k0 + 8, a_ok);
        uint32_t bd = (uint32_t)__cvta_generic_to_shared(
            &Bs[st][ldrow * HS_STRIDE + ldoff]);
        cp_async16(bd, b_src0 + k0, 16);
        cp_async16(bd + 16, b_src0 + k0 + 8, 16);
    };

    int lm_m = lane >> 3;
    int a_row = ((lm_m & 1) << 3) + (lane & 7);
    int a_kof = (lm_m >> 1) << 3;
    int b_nof = ((lane >> 4) & 1) << 3;
    int b_row = b_nof + (lane & 7);
    int b_kof = ((lane >> 3) & 1) << 3;

    float acc[4][4][4];
#pragma unroll
    for (int mi = 0; mi < 4; mi++)
#pragma unroll
        for (int ni = 0; ni < 4; ni++)
#pragma unroll
            for (int q = 0; q < 4; q++) acc[mi][ni][q] = 0.f;

    load_stage(0, 0);
    asm volatile("cp.async.commit_group;");
    load_stage(1, G1_BK);
    asm volatile("cp.async.commit_group;");

    for (int kt = 0; kt < G1_KT; kt++) {
        asm volatile("cp.async.wait_group 1;");
        __syncthreads();

        int buf = kt % STAGES;
        uint32_t as_base = (uint32_t)__cvta_generic_to_shared(&As[buf][0]);
        uint32_t bs_base = (uint32_t)__cvta_generic_to_shared(&Bs[buf][0]);
#pragma unroll
        for (int ks = 0; ks < 2; ks++) {
            int kk = ks * 16;
            uint32_t af[4][4], bf[4][2];
#pragma unroll
            for (int mi = 0; mi < 4; mi++) {
                int row = wm * 64 + mi * 16 + a_row;
                uint32_t addr = as_base + ((row * HS_STRIDE + kk + a_kof) << 1);
                asm volatile(
                    "ldmatrix.sync.aligned.m8n8.x4.shared.b16 {%0,%1,%2,%3}, [%4];"
                    : "=r"(af[mi][0]), "=r"(af[mi][1]),
                      "=r"(af[mi][2]), "=r"(af[mi][3])
                    : "r"(addr));
            }
#pragma unroll
            for (int p = 0; p < 2; p++) {
                int n = wn * 32 + p * 16 + b_row;
                uint32_t addr = bs_base + ((n * HS_STRIDE + kk + b_kof) << 1);
                uint32_t r0, r1, r2, r3;
                asm volatile(
                    "ldmatrix.sync.aligned.m8n8.x4.shared.b16 {%0,%1,%2,%3}, [%4];"
                    : "=r"(r0), "=r"(r1), "=r"(r2), "=r"(r3)
                    : "r"(addr));
                bf[2 * p][0] = r0;     bf[2 * p][1] = r1;
                bf[2 * p + 1][0] = r2; bf[2 * p + 1][1] = r3;
            }
#pragma unroll
            for (int mi = 0; mi < 4; mi++)
#pragma unroll
                for (int ni = 0; ni < 4; ni++)
                    mma_f16(acc[mi][ni], af[mi], bf[ni]);
        }
        if (kt + 2 < G1_KT) load_stage((kt + 2) % STAGES, (kt + 2) * G1_BK);
        asm volatile("cp.async.commit_group;");
    }

    // epilogue: scale by dinv[row], write p1 as fp8 e4m3 (2B stores)
#pragma unroll
    for (int mi = 0; mi < 4; mi++) {
        int r0 = brow + wm * 64 + mi * 16 + (lane >> 2);
        int r1 = r0 + 8;
        float dv0 = (r0 < N) ? g_dinv[r0] : 0.f;
        float dv1 = (r1 < N) ? g_dinv[r1] : 0.f;
#pragma unroll
        for (int ni = 0; ni < 4; ni++) {
            int c = bcol + wn * 32 + ni * 8 + (lane & 3) * 2;
            if (r0 < N) {
                unsigned short u = pack_e4m3x2(dv0 * acc[mi][ni][1],
                                               dv0 * acc[mi][ni][0]);
                *(unsigned short*)(g_p1f8 + (long)r0 * H1 + c) = u;
            }
            if (r1 < N) {
                unsigned short u = pack_e4m3x2(dv1 * acc[mi][ni][3],
                                               dv1 * acc[mi][ni][2]);
                *(unsigned short*)(g_p1f8 + (long)r1 * H1 + c) = u;
            }
        }
    }
}

// ---------------------------------------------------------------------------
// gather1 (F=256, fp8 src, fp16 dst): a1h[d] = relu(dinv[d]*(p1[d]+sum)+b1)
// 32 threads per node (uint2 = 8 fp8 each), 8 nodes per 256-thread block
// ---------------------------------------------------------------------------
__global__ void __launch_bounds__(256) gather1_kernel(const float* __restrict__ b1, int N) {
    int tid = threadIdx.x;
    int d = blockIdx.x * 8 + (tid >> 5);
    int lane = tid & 31;
    if (d >= N) return;

    const uint2* p1v = (const uint2*)g_p1f8;   // 32 uint2 per 256B row
    long rowbase = (long)d * 32;

    int start = g_rowstart[d];
    int deg = g_deg[d];

    __half2 acc0[4], acc1[4];
#pragma unroll
    for (int i = 0; i < 4; i++) {
        acc0[i] = __half2half2(__float2half(0.f));
        acc1[i] = acc0[i];
    }
    fp8x8_add(acc0, p1v[rowbase + lane]);      // self loop (pre-scaled)

    int j = 0;
    for (; j + 1 < deg; j += 2) {
        int s0 = __ldg(&g_csrc[start + j]);
        int s1 = __ldg(&g_csrc[start + j + 1]);
        uint2 v0 = p1v[(long)s0 * 32 + lane];
        uint2 v1 = p1v[(long)s1 * 32 + lane];
        fp8x8_add(acc0, v0);
        fp8x8_add(acc1, v1);
    }
    if (j < deg) {
        int s0 = __ldg(&g_csrc[start + j]);
        fp8x8_add(acc0, p1v[(long)s0 * 32 + lane]);
    }

    float dv = g_dinv[d];
    float4 ba = *(const float4*)&b1[lane * 8];
    float4 bb = *(const float4*)&b1[lane * 8 + 4];
    float o[8];
#pragma unroll
    for (int i = 0; i < 4; i++) {
        float2 f0 = __half22float2(acc0[i]);
        float2 f1 = __half22float2(acc1[i]);
        o[2 * i]     = dv * (f0.x + f1.x);
        o[2 * i + 1] = dv * (f0.y + f1.y);
    }
    o[0] += ba.x; o[1] += ba.y; o[2] += ba.z; o[3] += ba.w;
    o[4] += bb.x; o[5] += bb.y; o[6] += bb.z; o[7] += bb.w;
#pragma unroll
    for (int i = 0; i < 8; i++) o[i] = o[i] > 0.f ? o[i] : 0.f;

    uint4 vout;
    ((__half2*)&vout)[0] = __floats2half2_rn(o[0], o[1]);
    ((__half2*)&vout)[1] = __floats2half2_rn(o[2], o[3]);
    ((__half2*)&vout)[2] = __floats2half2_rn(o[4], o[5]);
    ((__half2*)&vout)[3] = __floats2half2_rn(o[6], o[7]);
    ((uint4*)g_a1h)[rowbase + lane] = vout;
}

// ---------------------------------------------------------------------------
// GEMM2: one thread per node. p2h[n] = fp16(dinv[n] * (a1h[n] @ W2))
// ---------------------------------------------------------------------------
__global__ void __launch_bounds__(256) gemm2_kernel(const float* __restrict__ W, int N) {
    __shared__ float Ws[H1 * H2];      // 16 KB
    int tid = threadIdx.x;
    for (int i = tid; i < H1 * H2; i += 256) Ws[i] = W[i];
    __syncthreads();

    int n = blockIdx.x * 256 + tid;
    if (n >= N) return;

    float acc[H2];
#pragma unroll
    for (int m = 0; m < H2; m++) acc[m] = 0.f;

    const uint4* arow = (const uint4*)(g_a1h + (long)n * H1);
    for (int k8 = 0; k8 < H1 / 8; k8++) {
        float f[8];
        h8unpack(f, arow[k8]);
        const float* wk = &Ws[k8 * 8 * H2];
#pragma unroll
        for (int m = 0; m < H2; m++) {
            float s = f[0] * wk[m]          + f[1] * wk[H2 + m] +
                      f[2] * wk[2 * H2 + m] + f[3] * wk[3 * H2 + m] +
                      f[4] * wk[4 * H2 + m] + f[5] * wk[5 * H2 + m] +
                      f[6] * wk[6 * H2 + m] + f[7] * wk[7 * H2 + m];
            acc[m] += s;
        }
    }

    float dv = g_dinv[n];
    uint4 v0, v1;
    ((__half2*)&v0)[0] = __floats2half2_rn(dv * acc[0], dv * acc[1]);
    ((__half2*)&v0)[1] = __floats2half2_rn(dv * acc[2], dv * acc[3]);
    ((__half2*)&v0)[2] = __floats2half2_rn(dv * acc[4], dv * acc[5]);
    ((__half2*)&v0)[3] = __floats2half2_rn(dv * acc[6], dv * acc[7]);
    ((__half2*)&v1)[0] = __floats2half2_rn(dv * acc[8], dv * acc[9]);
    ((__half2*)&v1)[1] = __floats2half2_rn(dv * acc[10], dv * acc[11]);
    ((__half2*)&v1)[2] = __floats2half2_rn(dv * acc[12], dv * acc[13]);
    ((__half2*)&v1)[3] = __floats2half2_rn(dv * acc[14], dv * acc[15]);
    ((uint4*)g_p2h)[(long)n * 2] = v0;
    ((uint4*)g_p2h)[(long)n * 2 + 1] = v1;
}

// ---------------------------------------------------------------------------
// gather2 (F=16, fp16): p3h[d] = fp16(dinv*relu(dinv*(p2[d]+sum p2[s]) + b2))
// 2 threads per node (uint4 = 8 halves each), 128 nodes per 256-thread block
// ---------------------------------------------------------------------------
__global__ void __launch_bounds__(256) gather2_kernel(const float* __restrict__ b2, int N) {
    int tid = threadIdx.x;
    int d = blockIdx.x * 128 + (tid >> 1);
    int half_ = tid & 1;
    if (d >= N) return;

    const uint4* p2v = (const uint4*)g_p2h;    // 2 uint4 per row
    int start = g_rowstart[d];
    int deg = g_deg[d];

    float acc0[8] = {0, 0, 0, 0, 0, 0, 0, 0};
    float acc1[8] = {0, 0, 0, 0, 0, 0, 0, 0};
    h8addf(acc0, p2v[(long)d * 2 + half_]);    // self loop

    int j = 0;
    for (; j + 1 < deg; j += 2) {
        int s0 = __ldg(&g_csrc[start + j]);
        int s1 = __ldg(&g_csrc[start + j + 1]);
        h8addf(acc0, p2v[(long)s0 * 2 + half_]);
        h8addf(acc1, p2v[(long)s1 * 2 + half_]);
    }
    if (j < deg) {
        int s0 = __ldg(&g_csrc[start + j]);
        h8addf(acc0, p2v[(long)s0 * 2 + half_]);
    }

    float dv = g_dinv[d];
    const float* bb = &b2[half_ * 8];
    uint4 vout;
#pragma unroll
    for (int i = 0; i < 4; i++) {
        float v0 = dv * (acc0[2 * i] + acc1[2 * i]) + bb[2 * i];
        float v1 = dv * (acc0[2 * i + 1] + acc1[2 * i + 1]) + bb[2 * i + 1];
        v0 = dv * (v0 > 0.f ? v0 : 0.f);
        v1 = dv * (v1 > 0.f ? v1 : 0.f);
        ((__half2*)&vout)[i] = __floats2half2_rn(v0, v1);
    }
    ((uint4*)g_p3h)[(long)d * 2 + half_] = vout;
}

// ---------------------------------------------------------------------------
// gather3 + final fused: a3 = dinv*(p3[d]+sum p3[s]);
// o = a3 @ W3 + b3 ; log_softmax. 2 threads per node, shfl pair-combine.
// ---------------------------------------------------------------------------
__global__ void __launch_bounds__(256) gather3_final_kernel(
    const float* __restrict__ W3, const float* __restrict__ b3,
    float* __restrict__ out, int N) {
    __shared__ float Ws[H2 * F_OUT];   // 640 floats
    __shared__ float bs[F_OUT];
    int tid = threadIdx.x;
    for (int i = tid; i < H2 * F_OUT; i += 256) Ws[i] = W3[i];
    if (tid < F_OUT) bs[tid] = b3[tid];
    __syncthreads();

    int draw = blockIdx.x * 128 + (tid >> 1);
    int half_ = tid & 1;
    bool valid = draw < N;
    int d = valid ? draw : (N - 1);    // clamp; keep lanes active for shfl

    const uint4* p3v = (const uint4*)g_p3h;
    int start = g_rowstart[d];
    int deg = g_deg[d];

    float acc0[8] = {0, 0, 0, 0, 0, 0, 0, 0};
    float acc1[8] = {0, 0, 0, 0, 0, 0, 0, 0};
    h8addf(acc0, p3v[(long)d * 2 + half_]);    // self loop

    int j = 0;
    for (; j + 1 < deg; j += 2) {
        int s0 = __ldg(&g_csrc[start + j]);
        int s1 = __ldg(&g_csrc[start + j + 1]);
        h8addf(acc0, p3v[(long)s0 * 2 + half_]);
        h8addf(acc1, p3v[(long)s1 * 2 + half_]);
    }
    if (j < deg) {
        int s0 = __ldg(&g_csrc[start + j]);
        h8addf(acc0, p3v[(long)s0 * 2 + half_]);
    }

    float dv = g_dinv[d];
    float a[8];
#pragma unroll
    for (int i = 0; i < 8; i++) a[i] = dv * (acc0[i] + acc1[i]);

    // partial logits over this thread's 8 k-values
    float o[F_OUT];
    const float* wbase = &Ws[half_ * 8 * F_OUT];
#pragma unroll
    for (int m = 0; m < F_OUT; m++) {
        float s = 0.f;
#pragma unroll
        for (int k = 0; k < 8; k++) s += a[k] * wbase[k * F_OUT + m];
        o[m] = s;
    }
    // combine with partner thread (same node)
#pragma unroll
    for (int m = 0; m < F_OUT; m++)
        o[m] += __shfl_xor_sync(0xffffffffu, o[m], 1);
#pragma unroll
    for (int m = 0; m < F_OUT; m++) o[m] += bs[m];

    float mx = o[0];
#pragma unroll
    for (int m = 1; m < F_OUT; m++) mx = fmaxf(mx, o[m]);
    float sum = 0.f;
#pragma unroll
    for (int m = 0; m < F_OUT; m++) sum += __expf(o[m] - mx);
    float lse = mx + __logf(sum);

    if (valid) {
        float* op = out + (long)draw * F_OUT;
        if (half_ == 0) {
#pragma unroll
            for (int m = 0; m < 20; m++) op[m] = o[m] - lse;
        } else {
#pragma unroll
            for (int m = 20; m < F_OUT; m++) op[m] = o[m] - lse;
        }
    }
}

// ---------------------------------------------------------------------------
// host launcher — kernel launches + event-forked side stream (capturable)
// ---------------------------------------------------------------------------
extern "C" void kernel_launch(void* const* d_in, const int* in_sizes, int n_in,
                              void* d_out, int out_size) {
    const float* x  = (const float*)d_in[0];
    const int*   ei = (const int*)d_in[1];      // int64 delivered as int32
    const float* W1 = (const float*)d_in[2];
    const float* b1 = (const float*)d_in[3];
    const float* W2 = (const float*)d_in[4];
    const float* b2 = (const float*)d_in[5];
    const float* W3 = (const float*)d_in[6];
    const float* b3 = (const float*)d_in[7];
    float* out = (float*)d_out;

    int N = in_sizes[0] / F_IN;
    int E = in_sizes[1] / 2;
    int nblk = (N + SCAN_B - 1) / SCAN_B;
    long total8 = (long)N * F_IN / 8;

    static cudaStream_t s1 = nullptr;
    static cudaEvent_t e_start = nullptr, e_conv = nullptr,
                       e_deg = nullptr, e_csr = nullptr;
    if (s1 == nullptr) {
        cudaStreamCreateWithFlags(&s1, cudaStreamNonBlocking);
        cudaEventCreateWithFlags(&e_start, cudaEventDisableTiming);
        cudaEventCreateWithFlags(&e_conv, cudaEventDisableTiming);
        cudaEventCreateWithFlags(&e_deg, cudaEventDisableTiming);
        cudaEventCreateWithFlags(&e_csr, cudaEventDisableTiming);
    }

    cudaEventRecord(e_start, 0);
    cudaStreamWaitEvent(s1, e_start, 0);

    // side: fp16 conversions
    convert_w1t_kernel<<<(H1 * F_IN + 255) / 256, 256, 0, s1>>>(W1);
    convert_x_kernel<<<(int)((total8 + 255) / 256), 256, 0, s1>>>(x, total8);
    cudaEventRecord(e_conv, s1);

    // main: degree + dinv
    zero_deg_kernel<<<(N + 255) / 256, 256>>>(N);
    count_deg_kernel<<<(E + 255) / 256, 256>>>(ei, E, N);
    cudaEventRecord(e_deg, 0);
    dinv_kernel<<<(N + 255) / 256, 256>>>(N);

    // side: CSR build
    cudaStreamWaitEvent(s1, e_deg, 0);
    scan_partial_kernel<<<nblk, SCAN_B, 0, s1>>>(N);
    scan_bsum_kernel<<<1, SCAN_B, 0, s1>>>(nblk);
    scan_add_kernel<<<(N + 255) / 256, 256, 0, s1>>>(N);
    csr_fill_kernel<<<(E + 255) / 256, 256, 0, s1>>>(ei, E, N);
    cudaEventRecord(e_csr, s1);

    // main: gemm1
    cudaStreamWaitEvent(0, e_conv, 0);
    {
        dim3 grid(H1 / G1_BN, (N + G1_BM - 1) / G1_BM);
        gemm1_kernel<<<grid, 256>>>(N);
    }

    // main: join CSR, aggregation chain
    cudaStreamWaitEvent(0, e_csr, 0);
    gather1_kernel<<<(N + 7) / 8, 256>>>(b1, N);
    gemm2_kernel<<<(N + 255) / 256, 256>>>(W2, N);
    gather2_kernel<<<(N + 127) / 128, 256>>>(b2, N);
    gather3_final_kernel<<<(N + 127) / 128, 256>>>(W3, b3, out, N);
}

// round 17
// speedup vs baseline: 1.3666x; 1.3666x over previous
#include <cuda_runtime.h>
#include <cuda_fp16.h>
#include <math.h>
#include <stdint.h>

// Problem constants (fixed for this problem instance)
#define NMAX   50000
#define EMAX   800000
#define F_IN   512
#define H1     256
#define H2     16
#define F_OUT  40

#define SCAN_B 256

// Scratch (static device arrays; no allocation allowed)
__device__ __half g_xh[NMAX * F_IN];  // x in fp16
__device__ __half g_w1t[H1 * F_IN];   // W1 transposed [m][k], fp16
__device__ __half g_p1h[NMAX * H1];   // dinv ⊙ (x @ W1), fp16
__device__ __half g_a1h[NMAX * H1];   // relu(Ahat h1 + b1), fp16
__device__ float g_p2[NMAX * H2];     // dinv ⊙ (a1 @ W2)
__device__ float g_p3[NMAX * H2];     // dinv ⊙ relu(Ahat h2 + b2)
__device__ int   g_deg[NMAX];
__device__ int   g_rowstart[NMAX];
__device__ int   g_cursor[NMAX];
__device__ int   g_csrc[EMAX];
__device__ int   g_bsum[SCAN_B];
__device__ float g_dinv[NMAX];

__device__ __forceinline__ float4 f4add(float4 a, float4 b) {
    return make_float4(a.x + b.x, a.y + b.y, a.z + b.z, a.w + b.w);
}

__device__ __forceinline__ void h8add(float acc[8], uint4 v) {
    const __half2* h = (const __half2*)&v;
#pragma unroll
    for (int i = 0; i < 4; i++) {
        float2 f = __half22float2(h[i]);
        acc[2 * i]     += f.x;
        acc[2 * i + 1] += f.y;
    }
}

__device__ __forceinline__ void h8unpack(float f[8], uint4 v) {
    const __half2* h = (const __half2*)&v;
#pragma unroll
    for (int i = 0; i < 4; i++) {
        float2 t = __half22float2(h[i]);
        f[2 * i] = t.x;
        f[2 * i + 1] = t.y;
    }
}

// ---------------------------------------------------------------------------
// conversions
// ---------------------------------------------------------------------------
__global__ void convert_x_kernel(const float* __restrict__ x, long total8) {
    long i = (long)blockIdx.x * blockDim.x + threadIdx.x;
    if (i < total8) {
        float4 a = ((const float4*)x)[2 * i];
        float4 b = ((const float4*)x)[2 * i + 1];
        uint4 v;
        ((__half2*)&v)[0] = __floats2half2_rn(a.x, a.y);
        ((__half2*)&v)[1] = __floats2half2_rn(a.z, a.w);
        ((__half2*)&v)[2] = __floats2half2_rn(b.x, b.y);
        ((__half2*)&v)[3] = __floats2half2_rn(b.z, b.w);
        ((uint4*)g_xh)[i] = v;
    }
}

__global__ void convert_w1t_kernel(const float* __restrict__ W1) {
    int i = blockIdx.x * blockDim.x + threadIdx.x;   // over H1*F_IN
    if (i < H1 * F_IN) {
        int m = i >> 9;          // /512
        int k = i & 511;
        g_w1t[i] = __float2half_rn(W1[k * H1 + m]);
    }
}

// ---------------------------------------------------------------------------
// degree / dinv / scan / CSR fill
// ---------------------------------------------------------------------------
__global__ void zero_deg_kernel(int N) {
    int i = blockIdx.x * blockDim.x + threadIdx.x;
    if (i < N) g_deg[i] = 0;
}

__global__ void count_deg_kernel(const int* __restrict__ ei, int E, int N) {
    int e = blockIdx.x * blockDim.x + threadIdx.x;
    if (e < E) {
        int d = ei[E + e];
        if ((unsigned)d < (unsigned)N) atomicAdd(&g_deg[d], 1);
    }
}

__global__ void dinv_kernel(int N) {
    int i = blockIdx.x * blockDim.x + threadIdx.x;
    if (i < N) g_dinv[i] = rsqrtf((float)(g_deg[i] + 1));   // +1 self-loop
}

__global__ void scan_partial_kernel(int N) {
    __shared__ int sd[SCAN_B];
    int t = threadIdx.x, b = blockIdx.x;
    int i = b * SCAN_B + t;
    int v = (i < N) ? g_deg[i] : 0;
    sd[t] = v;
    __syncthreads();
#pragma unroll
    for (int off = 1; off < SCAN_B; off <<= 1) {
        int x = (t >= off) ? sd[t - off] : 0;
        __syncthreads();
        sd[t] += x;
        __syncthreads();
    }
    if (i < N) g_rowstart[i] = sd[t] - v;       // exclusive
    if (t == SCAN_B - 1) g_bsum[b] = sd[t];
}

__global__ void scan_bsum_kernel(int nblk) {
    __shared__ int sd[SCAN_B];
    int t = threadIdx.x;
    int v = (t < nblk) ? g_bsum[t] : 0;
    sd[t] = v;
    __syncthreads();
#pragma unroll
    for (int off = 1; off < SCAN_B; off <<= 1) {
        int x = (t >= off) ? sd[t - off] : 0;
        __syncthreads();
        sd[t] += x;
        __syncthreads();
    }
    if (t < nblk) g_bsum[t] = sd[t] - v;
}

__global__ void scan_add_kernel(int N) {
    int i = blockIdx.x * blockDim.x + threadIdx.x;
    if (i < N) {
        int r = g_rowstart[i] + g_bsum[i / SCAN_B];
        g_rowstart[i] = r;
        g_cursor[i] = r;
    }
}

__global__ void csr_fill_kernel(const int* __restrict__ ei, int E, int N) {
    int e = blockIdx.x * blockDim.x + threadIdx.x;
    if (e < E) {
        int s = ei[e];
        int d = ei[E + e];
        if ((unsigned)s < (unsigned)N && (unsigned)d < (unsigned)N) {
            int pos = atomicAdd(&g_cursor[d], 1);
            g_csrc[pos] = s;
        }
    }
}

// ---------------------------------------------------------------------------
// GEMM1 (fp16 tensor cores, mma.m16n8k16, fp32 accum, cp.async 3-stage,
// ldmatrix for A and B): g_p1h = dinv ⊙ (xh @ W1)
// ---------------------------------------------------------------------------
#define G1_BM 128
#define G1_BN 128
#define G1_BK 32
#define G1_KT (F_IN / G1_BK)   // 16 k-tiles
#define STAGES 3
#define HS_STRIDE 40           // halves; 80B rows, conflict-free ldmatrix

__device__ __forceinline__ void mma_f16(float c[4], const uint32_t a[4],
                                        const uint32_t b[2]) {
    asm volatile(
        "mma.sync.aligned.m16n8k16.row.col.f32.f16.f16.f32 "
        "{%0,%1,%2,%3}, {%4,%5,%6,%7}, {%8,%9}, {%0,%1,%2,%3};"
        : "+f"(c[0]), "+f"(c[1]), "+f"(c[2]), "+f"(c[3])
        : "r"(a[0]), "r"(a[1]), "r"(a[2]), "r"(a[3]), "r"(b[0]), "r"(b[1]));
}

__device__ __forceinline__ void cp_async16(uint32_t smem_dst, const void* gsrc,
                                           int src_bytes) {
    asm volatile("cp.async.ca.shared.global [%0], [%1], 16, %2;"
                 :: "r"(smem_dst), "l"(gsrc), "r"(src_bytes));
}

__global__ void __launch_bounds__(256) gemm1_kernel(int N) {
    const int M = H1;
    __shared__ __half As[STAGES][G1_BM * HS_STRIDE];   // 30 KB
    __shared__ __half Bs[STAGES][G1_BN * HS_STRIDE];   // 30 KB

    int tid = threadIdx.x;
    int lane = tid & 31;
    int w = tid >> 5;
    int wm = w >> 2;
    int wn = w & 3;
    int brow = blockIdx.y * G1_BM;
    int bcol = blockIdx.x * G1_BN;

    int ldrow = tid >> 1;
    int ldoff = (tid & 1) * 16;

    int gr = brow + ldrow;
    int a_ok = (gr < N) ? 16 : 0;
    const __half* a_src0 = &g_xh[(long)gr * F_IN + ldoff];
    const __half* b_src0 = &g_w1t[(long)(bcol + ldrow) * F_IN + ldoff];

    auto load_stage = [&](int st, int k0) {
        uint32_t ad = (uint32_t)__cvta_generic_to_shared(
            &As[st][ldrow * HS_STRIDE + ldoff]);
        cp_async16(ad, a_src0 + k0, a_ok);
        cp_async16(ad + 16, a_src0 + k0 + 8, a_ok);
        uint32_t bd = (uint32_t)__cvta_generic_to_shared(
            &Bs[st][ldrow * HS_STRIDE + ldoff]);
        cp_async16(bd, b_src0 + k0, 16);
        cp_async16(bd + 16, b_src0 + k0 + 8, 16);
    };

    int lm_m = lane >> 3;
    int a_row = ((lm_m & 1) << 3) + (lane & 7);
    int a_kof = (lm_m >> 1) << 3;
    int b_nof = ((lane >> 4) & 1) << 3;
    int b_row = b_nof + (lane & 7);
    int b_kof = ((lane >> 3) & 1) << 3;

    float acc[4][4][4];
#pragma unroll
    for (int mi = 0; mi < 4; mi++)
#pragma unroll
        for (int ni = 0; ni < 4; ni++)
#pragma unroll
            for (int q = 0; q < 4; q++) acc[mi][ni][q] = 0.f;

    load_stage(0, 0);
    asm volatile("cp.async.commit_group;");
    load_stage(1, G1_BK);
    asm volatile("cp.async.commit_group;");

    for (int kt = 0; kt < G1_KT; kt++) {
        asm volatile("cp.async.wait_group 1;");
        __syncthreads();

        int buf = kt % STAGES;
        uint32_t as_base = (uint32_t)__cvta_generic_to_shared(&As[buf][0]);
        uint32_t bs_base = (uint32_t)__cvta_generic_to_shared(&Bs[buf][0]);
#pragma unroll
        for (int ks = 0; ks < 2; ks++) {
            int kk = ks * 16;
            uint32_t af[4][4], bf[4][2];
#pragma unroll
            for (int mi = 0; mi < 4; mi++) {
                int row = wm * 64 + mi * 16 + a_row;
                uint32_t addr = as_base + ((row * HS_STRIDE + kk + a_kof) << 1);
                asm volatile(
                    "ldmatrix.sync.aligned.m8n8.x4.shared.b16 {%0,%1,%2,%3}, [%4];"
                    : "=r"(af[mi][0]), "=r"(af[mi][1]),
                      "=r"(af[mi][2]), "=r"(af[mi][3])
                    : "r"(addr));
            }
#pragma unroll
            for (int p = 0; p < 2; p++) {
                int n = wn * 32 + p * 16 + b_row;
                uint32_t addr = bs_base + ((n * HS_STRIDE + kk + b_kof) << 1);
                uint32_t r0, r1, r2, r3;
                asm volatile(
                    "ldmatrix.sync.aligned.m8n8.x4.shared.b16 {%0,%1,%2,%3}, [%4];"
                    : "=r"(r0), "=r"(r1), "=r"(r2), "=r"(r3)
                    : "r"(addr));
                bf[2 * p][0] = r0;     bf[2 * p][1] = r1;
                bf[2 * p + 1][0] = r2; bf[2 * p + 1][1] = r3;
            }
#pragma unroll
            for (int mi = 0; mi < 4; mi++)
#pragma unroll
                for (int ni = 0; ni < 4; ni++)
                    mma_f16(acc[mi][ni], af[mi], bf[ni]);
        }
        if (kt + 2 < G1_KT) load_stage((kt + 2) % STAGES, (kt + 2) * G1_BK);
        asm volatile("cp.async.commit_group;");
    }

#pragma unroll
    for (int mi = 0; mi < 4; mi++) {
        int r0 = brow + wm * 64 + mi * 16 + (lane >> 2);
        int r1 = r0 + 8;
        float dv0 = (r0 < N) ? g_dinv[r0] : 0.f;
        float dv1 = (r1 < N) ? g_dinv[r1] : 0.f;
#pragma unroll
        for (int ni = 0; ni < 4; ni++) {
            int c = bcol + wn * 32 + ni * 8 + (lane & 3) * 2;
            if (r0 < N) {
                __half2 v = __floats2half2_rn(dv0 * acc[mi][ni][0],
                                              dv0 * acc[mi][ni][1]);
                *(__half2*)&g_p1h[(long)r0 * M + c] = v;
            }
            if (r1 < N) {
                __half2 v = __floats2half2_rn(dv1 * acc[mi][ni][2],
                                              dv1 * acc[mi][ni][3]);
                *(__half2*)&g_p1h[(long)r1 * M + c] = v;
            }
        }
    }
}

// ---------------------------------------------------------------------------
// gather1 (F=256, fp16 src AND dst): a1h[d] = relu(dinv[d]*(p1[d]+sum)+b1)
// 32 threads per node (uint4 = 8 halves each), 8 nodes per 256-thread block
// ---------------------------------------------------------------------------
__global__ void __launch_bounds__(256) gather1_kernel(const float* __restrict__ b1, int N) {
    int tid = threadIdx.x;
    int d = blockIdx.x * 8 + (tid >> 5);
    int lane = tid & 31;
    if (d >= N) return;

    const uint4* p1v = (const uint4*)g_p1h;
    long rowbase = (long)d * 32;

    int start = g_rowstart[d];
    int deg = g_deg[d];

    float acc0[8], acc1[8];
    {
        uint4 v = p1v[rowbase + lane];
        const __half2* h = (const __half2*)&v;
#pragma unroll
        for (int i = 0; i < 4; i++) {
            float2 f = __half22float2(h[i]);
            acc0[2 * i] = f.x; acc0[2 * i + 1] = f.y;
            acc1[2 * i] = 0.f; acc1[2 * i + 1] = 0.f;
        }
    }

    int j = 0;
    for (; j + 1 < deg; j += 2) {
        int s0 = __ldg(&g_csrc[start + j]);
        int s1 = __ldg(&g_csrc[start + j + 1]);
        uint4 v0 = p1v[(long)s0 * 32 + lane];
        uint4 v1 = p1v[(long)s1 * 32 + lane];
        h8add(acc0, v0);
        h8add(acc1, v1);
    }
    if (j < deg) {
        int s0 = __ldg(&g_csrc[start + j]);
        h8add(acc0, p1v[(long)s0 * 32 + lane]);
    }

    float dv = g_dinv[d];
    float4 ba = *(const float4*)&b1[lane * 8];
    float4 bb = *(const float4*)&b1[lane * 8 + 4];
    float o[8];
#pragma unroll
    for (int i = 0; i < 8; i++) o[i] = dv * (acc0[i] + acc1[i]);
    o[0] += ba.x; o[1] += ba.y; o[2] += ba.z; o[3] += ba.w;
    o[4] += bb.x; o[5] += bb.y; o[6] += bb.z; o[7] += bb.w;
#pragma unroll
    for (int i = 0; i < 8; i++) o[i] = o[i] > 0.f ? o[i] : 0.f;

    uint4 vout;
    ((__half2*)&vout)[0] = __floats2half2_rn(o[0], o[1]);
    ((__half2*)&vout)[1] = __floats2half2_rn(o[2], o[3]);
    ((__half2*)&vout)[2] = __floats2half2_rn(o[4], o[5]);
    ((__half2*)&vout)[3] = __floats2half2_rn(o[6], o[7]);
    ((uint4*)g_a1h)[rowbase + lane] = vout;
}

// ---------------------------------------------------------------------------
// GEMM2: one thread per node. p2[n] = dinv[n] * (a1h[n] @ W2), fp16 input
// ---------------------------------------------------------------------------
__global__ void __launch_bounds__(256) gemm2_kernel(const float* __restrict__ W, int N) {
    __shared__ float Ws[H1 * H2];      // 16 KB
    int tid = threadIdx.x;
    for (int i = tid; i < H1 * H2; i += 256) Ws[i] = W[i];
    __syncthreads();

    int n = blockIdx.x * 256 + tid;
    if (n >= N) return;

    float acc[H2];
#pragma unroll
    for (int m = 0; m < H2; m++) acc[m] = 0.f;

    const uint4* arow = (const uint4*)(g_a1h + (long)n * H1);  // 32 uint4/row
    for (int k8 = 0; k8 < H1 / 8; k8++) {
        float f[8];
        h8unpack(f, arow[k8]);
        const float* wk = &Ws[k8 * 8 * H2];
#pragma unroll
        for (int m = 0; m < H2; m++) {
            float s = f[0] * wk[m]          + f[1] * wk[H2 + m] +
                      f[2] * wk[2 * H2 + m] + f[3] * wk[3 * H2 + m] +
                      f[4] * wk[4 * H2 + m] + f[5] * wk[5 * H2 + m] +
                      f[6] * wk[6 * H2 + m] + f[7] * wk[7 * H2 + m];
            acc[m] += s;
        }
    }

    float dv = g_dinv[n];
    float* op = &g_p2[(long)n * H2];
#pragma unroll
    for (int m4 = 0; m4 < 4; m4++) {
        float4 v = make_float4(dv * acc[m4 * 4 + 0], dv * acc[m4 * 4 + 1],
                               dv * acc[m4 * 4 + 2], dv * acc[m4 * 4 + 3]);
        *(float4*)&op[m4 * 4] = v;
    }
}

// ---------------------------------------------------------------------------
// gather2 (F=16, float4): p3[d] = dinv[d]*relu(dinv[d]*(p2[d]+sum p2[s]) + b2)
// 4 threads per node, 64 nodes per 256-thread block
// ---------------------------------------------------------------------------
__global__ void __launch_bounds__(256) gather2_kernel(const float* __restrict__ b2, int N) {
    int tid = threadIdx.x;
    int d = blockIdx.x * 64 + (tid >> 2);
    int f4 = tid & 3;
    if (d >= N) return;

    const float4* p2v = (const float4*)g_p2;
    int start = g_rowstart[d];
    int deg = g_deg[d];

    float4 acc0 = p2v[(long)d * 4 + f4];
    float4 acc1 = make_float4(0.f, 0.f, 0.f, 0.f);
    int j = 0;
    for (; j + 1 < deg; j += 2) {
        int s0 = __ldg(&g_csrc[start + j]);
        int s1 = __ldg(&g_csrc[start + j + 1]);
        acc0 = f4add(acc0, p2v[(long)s0 * 4 + f4]);
        acc1 = f4add(acc1, p2v[(long)s1 * 4 + f4]);
    }
    if (j < deg) {
        int s0 = __ldg(&g_csrc[start + j]);
        acc0 = f4add(acc0, p2v[(long)s0 * 4 + f4]);
    }

    float dv = g_dinv[d];
    float4 bb = ((const float4*)b2)[f4];
    float4 v = make_float4(dv * (acc0.x + acc1.x) + bb.x,
                           dv * (acc0.y + acc1.y) + bb.y,
                           dv * (acc0.z + acc1.z) + bb.z,
                           dv * (acc0.w + acc1.w) + bb.w);
    v.x = dv * (v.x > 0.f ? v.x : 0.f);
    v.y = dv * (v.y > 0.f ? v.y : 0.f);
    v.z = dv * (v.z > 0.f ? v.z : 0.f);
    v.w = dv * (v.w > 0.f ? v.w : 0.f);
    ((float4*)g_p3)[(long)d * 4 + f4] = v;
}

// ---------------------------------------------------------------------------
// gather3 + final fused: a3 = dinv*(p3[d]+sum p3[s]);
// o = a3 @ W3 + b3 ; log_softmax. 2 threads/node (2 float4 each), shfl combine.
// ---------------------------------------------------------------------------
__global__ void __launch_bounds__(256) gather3_final_kernel(
    const float* __restrict__ W3, const float* __restrict__ b3,
    float* __restrict__ out, int N) {
    __shared__ float Ws[H2 * F_OUT];   // 640 floats
    __shared__ float bs[F_OUT];
    int tid = threadIdx.x;
    for (int i = tid; i < H2 * F_OUT; i += 256) Ws[i] = W3[i];
    if (tid < F_OUT) bs[tid] = b3[tid];
    __syncthreads();

    int draw = blockIdx.x * 128 + (tid >> 1);
    int half_ = tid & 1;
    bool valid = draw < N;
    int d = valid ? draw : (N - 1);    // clamp; keep lanes active for shfl

    const float4* p3v = (const float4*)g_p3;   // 4 float4 per row
    long base = (long)d * 4 + half_ * 2;
    int start = g_rowstart[d];
    int deg = g_deg[d];

    float4 a0 = p3v[base];             // self loop
    float4 a1 = p3v[base + 1];
    float4 b0 = make_float4(0.f, 0.f, 0.f, 0.f);
    float4 b1v = b0;
    int j = 0;
    for (; j + 1 < deg; j += 2) {
        int s0 = __ldg(&g_csrc[start + j]);
        int s1 = __ldg(&g_csrc[start + j + 1]);
        long o0 = (long)s0 * 4 + half_ * 2;
        long o1 = (long)s1 * 4 + half_ * 2;
        a0 = f4add(a0, p3v[o0]);
        a1 = f4add(a1, p3v[o0 + 1]);
        b0 = f4add(b0, p3v[o1]);
        b1v = f4add(b1v, p3v[o1 + 1]);
    }
    if (j < deg) {
        int s0 = __ldg(&g_csrc[start + j]);
        long o0 = (long)s0 * 4 + half_ * 2;
        a0 = f4add(a0, p3v[o0]);
        a1 = f4add(a1, p3v[o0 + 1]);
    }

    float dv = g_dinv[d];
    float a[8];
    a[0] = dv * (a0.x + b0.x); a[1] = dv * (a0.y + b0.y);
    a[2] = dv * (a0.z + b0.z); a[3] = dv * (a0.w + b0.w);
    a[4] = dv * (a1.x + b1v.x); a[5] = dv * (a1.y + b1v.y);
    a[6] = dv * (a1.z + b1v.z); a[7] = dv * (a1.w + b1v.w);

    // partial logits over this thread's 8 k-values
    float o[F_OUT];
    const float* wbase = &Ws[half_ * 8 * F_OUT];
#pragma unroll
    for (int m = 0; m < F_OUT; m++) {
        float s = 0.f;
#pragma unroll
        for (int k = 0; k < 8; k++) s += a[k] * wbase[k * F_OUT + m];
        o[m] = s;
    }
    // combine with partner thread (same node)
#pragma unroll
    for (int m = 0; m < F_OUT; m++)
        o[m] += __shfl_xor_sync(0xffffffffu, o[m], 1);
#pragma unroll
    for (int m = 0; m < F_OUT; m++) o[m] += bs[m];

    float mx = o[0];
#pragma unroll
    for (int m = 1; m < F_OUT; m++) mx = fmaxf(mx, o[m]);
    float sum = 0.f;
#pragma unroll
    for (int m = 0; m < F_OUT; m++) sum += __expf(o[m] - mx);
    float lse = mx + __logf(sum);

    if (valid) {
        float* op = out + (long)draw * F_OUT;
        if (half_ == 0) {
#pragma unroll
            for (int m = 0; m < 20; m++) op[m] = o[m] - lse;
        } else {
#pragma unroll
            for (int m = 20; m < F_OUT; m++) op[m] = o[m] - lse;
        }
    }
}

// ---------------------------------------------------------------------------
// host launcher — kernel launches + event-forked side stream (capturable)
// ---------------------------------------------------------------------------
extern "C" void kernel_launch(void* const* d_in, const int* in_sizes, int n_in,
                              void* d_out, int out_size) {
    const float* x  = (const float*)d_in[0];
    const int*   ei = (const int*)d_in[1];      // int64 delivered as int32
    const float* W1 = (const float*)d_in[2];
    const float* b1 = (const float*)d_in[3];
    const float* W2 = (const float*)d_in[4];
    const float* b2 = (const float*)d_in[5];
    const float* W3 = (const float*)d_in[6];
    const float* b3 = (const float*)d_in[7];
    float* out = (float*)d_out;

    int N = in_sizes[0] / F_IN;
    int E = in_sizes[1] / 2;
    int nblk = (N + SCAN_B - 1) / SCAN_B;
    long total8 = (long)N * F_IN / 8;

    static cudaStream_t s1 = nullptr;
    static cudaEvent_t e_start = nullptr, e_conv = nullptr,
                       e_deg = nullptr, e_csr = nullptr;
    if (s1 == nullptr) {
        cudaStreamCreateWithFlags(&s1, cudaStreamNonBlocking);
        cudaEventCreateWithFlags(&e_start, cudaEventDisableTiming);
        cudaEventCreateWithFlags(&e_conv, cudaEventDisableTiming);
        cudaEventCreateWithFlags(&e_deg, cudaEventDisableTiming);
        cudaEventCreateWithFlags(&e_csr, cudaEventDisableTiming);
    }

    cudaEventRecord(e_start, 0);
    cudaStreamWaitEvent(s1, e_start, 0);

    // side: fp16 conversions
    convert_w1t_kernel<<<(H1 * F_IN + 255) / 256, 256, 0, s1>>>(W1);
    convert_x_kernel<<<(int)((total8 + 255) / 256), 256, 0, s1>>>(x, total8);
    cudaEventRecord(e_conv, s1);

    // main: degree + dinv
    zero_deg_kernel<<<(N + 255) / 256, 256>>>(N);
    count_deg_kernel<<<(E + 255) / 256, 256>>>(ei, E, N);
    cudaEventRecord(e_deg, 0);
    dinv_kernel<<<(N + 255) / 256, 256>>>(N);

    // side: CSR build
    cudaStreamWaitEvent(s1, e_deg, 0);
    scan_partial_kernel<<<nblk, SCAN_B, 0, s1>>>(N);
    scan_bsum_kernel<<<1, SCAN_B, 0, s1>>>(nblk);
    scan_add_kernel<<<(N + 255) / 256, 256, 0, s1>>>(N);
    csr_fill_kernel<<<(E + 255) / 256, 256, 0, s1>>>(ei, E, N);
    cudaEventRecord(e_csr, s1);

    // main: gemm1
    cudaStreamWaitEvent(0, e_conv, 0);
    {
        dim3 grid(H1 / G1_BN, (N + G1_BM - 1) / G1_BM);
        gemm1_kernel<<<grid, 256>>>(N);
    }

    // main: join CSR, aggregation chain
    cudaStreamWaitEvent(0, e_csr, 0);
    gather1_kernel<<<(N + 7) / 8, 256>>>(b1, N);
    gemm2_kernel<<<(N + 255) / 256, 256>>>(W2, N);
    gather2_kernel<<<(N + 63) / 64, 256>>>(b2, N);
    gather3_final_kernel<<<(N + 127) / 128, 256>>>(W3, b3, out, N);
}